// round 1
// baseline (speedup 1.0000x reference)
#include <cuda_runtime.h>
#include <cstdint>

#define NN 100000
#define EE 600000
#define DD 128

// Scratch (allocation-free: __device__ globals)
__device__ float g_hs[(size_t)NN * DD];   // (X @ W) * dinv[row]
__device__ float g_acc[(size_t)NN * DD];  // scatter accumulator
__device__ float g_deg[NN];
__device__ float g_dinv[NN];
__device__ int   g_is64;                  // edge_index dtype flag

// ---------------------------------------------------------------------------
// Detect whether edge_index is int64 or int32.
// If int64 (little-endian), the high 32-bit word of every value < 2^32 is 0.
// Sample odd 32-bit words within the first 2*EE words (safe for both dtypes).
__global__ void detect_kernel(const int* __restrict__ w) {
    __shared__ int s_any;
    if (threadIdx.x == 0) s_any = 0;
    __syncthreads();
    int acc = 0;
    for (int k = threadIdx.x; k < 4096; k += 256) {
        acc |= w[2 * (k * 137) + 1];   // max index 1,122,031 < 1,200,000
    }
    if (acc) atomicOr(&s_any, 1);
    __syncthreads();
    if (threadIdx.x == 0) g_is64 = (s_any == 0) ? 1 : 0;
}

__device__ __forceinline__ long long load_edge(const void* ei, long long pos) {
    if (g_is64) return ((const long long*)ei)[pos];
    return (long long)((const int*)ei)[pos];
}

// ---------------------------------------------------------------------------
// Degree (in-degree over dst, +1 for self loop) and dinv = rsqrt(deg)
__global__ void init_deg_kernel() {
    int i = blockIdx.x * blockDim.x + threadIdx.x;
    if (i < NN) g_deg[i] = 1.0f;   // self loop
}

__global__ void count_deg_kernel(const void* __restrict__ ei) {
    int e = blockIdx.x * blockDim.x + threadIdx.x;
    if (e >= EE) return;
    long long d = load_edge(ei, (long long)EE + e);
    atomicAdd(&g_deg[d], 1.0f);
}

__global__ void dinv_kernel() {
    int i = blockIdx.x * blockDim.x + threadIdx.x;
    if (i < NN) g_dinv[i] = rsqrtf(g_deg[i]);
}

// ---------------------------------------------------------------------------
// GEMM: g_hs[r,:] = (X[r,:] @ W) * g_dinv[r];  also zeroes g_acc[r,:].
// Tile: 64 rows x 128 cols, full K=128 in one pass. 256 threads,
// thread tile 8x4. smem: sX 64x128 (32KB) + sW 128x128 (64KB) = 96KB dynamic.
__global__ __launch_bounds__(256, 2)
void gemm_scale_kernel(const float* __restrict__ X, const float* __restrict__ W) {
    extern __shared__ float smem[];
    float* sX = smem;            // [64][128]
    float* sW = smem + 64 * DD;  // [128][128]

    const int tid  = threadIdx.x;
    const int row0 = blockIdx.x * 64;

    // Load W (4096 float4, 16 per thread)
    {
        const float4* Wv = (const float4*)W;
        float4* sWv = (float4*)sW;
        #pragma unroll
        for (int i = 0; i < 16; i++) sWv[tid + i * 256] = Wv[tid + i * 256];
    }
    // Load X tile (2048 float4, 8 per thread), zero-pad past NN
    {
        #pragma unroll
        for (int i = 0; i < 8; i++) {
            int t4 = tid + i * 256;      // 0..2047
            int r  = t4 >> 5;            // row in tile
            int c4 = t4 & 31;            // float4 column
            float4 v = make_float4(0.f, 0.f, 0.f, 0.f);
            if (row0 + r < NN)
                v = ((const float4*)(X + (size_t)(row0 + r) * DD))[c4];
            ((float4*)(sX + r * DD))[c4] = v;
        }
    }
    __syncthreads();

    const int ty = tid >> 5;   // 0..7  -> rows ty*8 .. ty*8+7
    const int tx = tid & 31;   // 0..31 -> cols tx*4 .. tx*4+3

    float c[8][4];
    #pragma unroll
    for (int m = 0; m < 8; m++)
        #pragma unroll
        for (int n = 0; n < 4; n++) c[m][n] = 0.0f;

    #pragma unroll 4
    for (int k = 0; k < DD; k++) {
        float4 b = ((const float4*)(sW + k * DD))[tx];
        float a[8];
        #pragma unroll
        for (int m = 0; m < 8; m++) a[m] = sX[(ty * 8 + m) * DD + k];  // broadcast
        #pragma unroll
        for (int m = 0; m < 8; m++) {
            c[m][0] += a[m] * b.x;
            c[m][1] += a[m] * b.y;
            c[m][2] += a[m] * b.z;
            c[m][3] += a[m] * b.w;
        }
    }

    #pragma unroll
    for (int m = 0; m < 8; m++) {
        int r = row0 + ty * 8 + m;
        if (r < NN) {
            float di = g_dinv[r];
            float4 o = make_float4(c[m][0] * di, c[m][1] * di,
                                   c[m][2] * di, c[m][3] * di);
            ((float4*)(g_hs  + (size_t)r * DD))[tx] = o;
            ((float4*)(g_acc + (size_t)r * DD))[tx] = make_float4(0.f, 0.f, 0.f, 0.f);
        }
    }
}

// ---------------------------------------------------------------------------
// Scatter: one warp per edge; lane handles 4 consecutive floats.
// acc[dst] += hs[src]  via red.global.add.v4.f32 (4x fewer L2 atomic ops).
__global__ void scatter_kernel(const void* __restrict__ ei) {
    const int gid  = blockIdx.x * blockDim.x + threadIdx.x;
    const int e    = gid >> 5;
    const int lane = gid & 31;
    if (e >= EE) return;

    long long s = load_edge(ei, e);
    long long d = load_edge(ei, (long long)EE + e);

    const float4 v = ((const float4*)(g_hs + (size_t)s * DD))[lane];
    float* p = g_acc + (size_t)d * DD + 4 * lane;
    asm volatile("red.global.add.v4.f32 [%0], {%1,%2,%3,%4};"
                 :: "l"(p), "f"(v.x), "f"(v.y), "f"(v.z), "f"(v.w)
                 : "memory");
}

// ---------------------------------------------------------------------------
// Finalize: out[i,:] = (acc[i,:] + hs[i,:]) * dinv[i] + b[:]   (hs term = self loop)
template <bool RELU>
__global__ void finalize_kernel(const float* __restrict__ bvec,
                                float* __restrict__ out) {
    int idx = blockIdx.x * blockDim.x + threadIdx.x;   // over NN*32 float4s
    if (idx >= NN * 32) return;
    int i  = idx >> 5;
    int c4 = idx & 31;
    float4 a = ((const float4*)g_acc)[idx];
    float4 h = ((const float4*)g_hs)[idx];
    float  di = g_dinv[i];
    float4 b = ((const float4*)bvec)[c4];
    float4 r;
    r.x = (a.x + h.x) * di + b.x;
    r.y = (a.y + h.y) * di + b.y;
    r.z = (a.z + h.z) * di + b.z;
    r.w = (a.w + h.w) * di + b.w;
    if (RELU) {
        r.x = fmaxf(r.x, 0.f);
        r.y = fmaxf(r.y, 0.f);
        r.z = fmaxf(r.z, 0.f);
        r.w = fmaxf(r.w, 0.f);
    }
    ((float4*)out)[idx] = r;
}

// ---------------------------------------------------------------------------
extern "C" void kernel_launch(void* const* d_in, const int* in_sizes, int n_in,
                              void* d_out, int out_size) {
    const float* x  = (const float*)d_in[0];
    const float* W1 = (const float*)d_in[1];
    const float* b1 = (const float*)d_in[2];
    const float* W2 = (const float*)d_in[3];
    const float* b2 = (const float*)d_in[4];
    const void*  ei = d_in[5];
    float* out = (float*)d_out;

    (void)in_sizes; (void)n_in; (void)out_size;

    const int SMEM = 96 * 1024;
    cudaFuncSetAttribute(gemm_scale_kernel,
                         cudaFuncAttributeMaxDynamicSharedMemorySize, SMEM);

    detect_kernel<<<1, 256>>>((const int*)ei);

    init_deg_kernel<<<(NN + 255) / 256, 256>>>();
    count_deg_kernel<<<(EE + 255) / 256, 256>>>(ei);
    dinv_kernel<<<(NN + 255) / 256, 256>>>();

    const int GEMM_BLOCKS = (NN + 63) / 64;
    const int SCAT_BLOCKS = (EE * 32) / 256;           // 75000 exactly
    const int FIN_BLOCKS  = (NN * 32 + 255) / 256;

    // Layer 1
    gemm_scale_kernel<<<GEMM_BLOCKS, 256, SMEM>>>(x, W1);
    scatter_kernel<<<SCAT_BLOCKS, 256>>>(ei);
    finalize_kernel<true><<<FIN_BLOCKS, 256>>>(b1, out);

    // Layer 2 (reads layer-1 output from d_out, stream-ordered)
    gemm_scale_kernel<<<GEMM_BLOCKS, 256, SMEM>>>(out, W2);
    scatter_kernel<<<SCAT_BLOCKS, 256>>>(ei);
    finalize_kernel<false><<<FIN_BLOCKS, 256>>>(b2, out);
}

// round 2
// speedup vs baseline: 1.4125x; 1.4125x over previous
#include <cuda_runtime.h>
#include <cstdint>

#define NN 100000
#define EE 600000
#define DD 128

#define SCAN_CHUNK 1024
#define NBLK_SCAN ((NN + SCAN_CHUNK - 1) / SCAN_CHUNK)   // 98

// Scratch (allocation-free: __device__ globals)
__device__ float g_hs[(size_t)NN * DD];   // (X @ W) * dinv[row]
__device__ float g_dinv[NN];
__device__ int   g_cnt[NN];               // in-degree (excl self loop)
__device__ int   g_rowptr[NN];            // CSR row starts
__device__ int   g_fill[NN];              // fill cursors
__device__ int   g_srcidx[EE];            // CSR column (src) indices
__device__ int   g_bsums[NBLK_SCAN];
__device__ int   g_boffs[NBLK_SCAN];
__device__ int   g_is64;                  // edge_index dtype flag

// ---------------------------------------------------------------------------
// Detect whether edge_index is int64 or int32 (little-endian high words zero).
__global__ void detect_kernel(const int* __restrict__ w) {
    __shared__ int s_any;
    if (threadIdx.x == 0) s_any = 0;
    __syncthreads();
    int acc = 0;
    for (int k = threadIdx.x; k < 4096; k += 256) {
        acc |= w[2 * (k * 137) + 1];   // max index < 2*EE for both dtypes
    }
    if (acc) atomicOr(&s_any, 1);
    __syncthreads();
    if (threadIdx.x == 0) g_is64 = (s_any == 0) ? 1 : 0;
}

__device__ __forceinline__ int load_edge(const void* ei, long long pos) {
    if (g_is64) return (int)((const long long*)ei)[pos];
    return ((const int*)ei)[pos];
}

// ---------------------------------------------------------------------------
// CSR build
__global__ void zero_cnt_kernel() {
    int i = blockIdx.x * blockDim.x + threadIdx.x;
    if (i < NN) g_cnt[i] = 0;
}

__global__ void hist_kernel(const void* __restrict__ ei) {
    int e = blockIdx.x * blockDim.x + threadIdx.x;
    if (e >= EE) return;
    int d = load_edge(ei, (long long)EE + e);
    atomicAdd(&g_cnt[d], 1);
}

// Block-level exclusive scan over chunks of 1024 (256 thr x 4 elems)
__global__ __launch_bounds__(256)
void scan1_kernel() {
    __shared__ int s_warp[8];
    const int tid  = threadIdx.x;
    const int base = blockIdx.x * SCAN_CHUNK + tid * 4;

    int v0 = (base + 0 < NN) ? g_cnt[base + 0] : 0;
    int v1 = (base + 1 < NN) ? g_cnt[base + 1] : 0;
    int v2 = (base + 2 < NN) ? g_cnt[base + 2] : 0;
    int v3 = (base + 3 < NN) ? g_cnt[base + 3] : 0;
    int tsum = v0 + v1 + v2 + v3;

    // warp inclusive scan of tsum
    int lane = tid & 31, wid = tid >> 5;
    int incl = tsum;
    #pragma unroll
    for (int o = 1; o < 32; o <<= 1) {
        int n = __shfl_up_sync(0xffffffffu, incl, o);
        if (lane >= o) incl += n;
    }
    if (lane == 31) s_warp[wid] = incl;
    __syncthreads();
    if (wid == 0) {
        int w = (lane < 8) ? s_warp[lane] : 0;
        int wi = w;
        #pragma unroll
        for (int o = 1; o < 8; o <<= 1) {
            int n = __shfl_up_sync(0xffffffffu, wi, o);
            if (lane >= o) wi += n;
        }
        if (lane < 8) s_warp[lane] = wi - w;   // exclusive warp offsets
        if (lane == 7 && blockIdx.x < NBLK_SCAN) g_bsums[blockIdx.x] = wi; // block total
    }
    __syncthreads();

    int off = s_warp[wid] + (incl - tsum);     // exclusive offset for this thread
    if (base + 0 < NN) g_rowptr[base + 0] = off;
    if (base + 1 < NN) g_rowptr[base + 1] = off + v0;
    if (base + 2 < NN) g_rowptr[base + 2] = off + v0 + v1;
    if (base + 3 < NN) g_rowptr[base + 3] = off + v0 + v1 + v2;
}

// Scan the 98 block sums (single block, Hillis-Steele in smem)
__global__ __launch_bounds__(128)
void scan2_kernel() {
    __shared__ int s[128];
    int t = threadIdx.x;
    int v = (t < NBLK_SCAN) ? g_bsums[t] : 0;
    s[t] = v;
    __syncthreads();
    #pragma unroll
    for (int o = 1; o < 128; o <<= 1) {
        int add = (t >= o) ? s[t - o] : 0;
        __syncthreads();
        s[t] += add;
        __syncthreads();
    }
    if (t < NBLK_SCAN) g_boffs[t] = s[t] - v;  // exclusive
}

// Add block offsets; init fill cursors; compute dinv
__global__ void scan3_kernel() {
    int i = blockIdx.x * blockDim.x + threadIdx.x;
    if (i >= NN) return;
    int rp = g_rowptr[i] + g_boffs[i / SCAN_CHUNK];
    g_rowptr[i] = rp;
    g_fill[i]   = rp;
    g_dinv[i]   = rsqrtf((float)(g_cnt[i] + 1));   // +1 self loop
}

__global__ void fill_kernel(const void* __restrict__ ei) {
    int e = blockIdx.x * blockDim.x + threadIdx.x;
    if (e >= EE) return;
    int s = load_edge(ei, e);
    int d = load_edge(ei, (long long)EE + e);
    int pos = atomicAdd(&g_fill[d], 1);
    g_srcidx[pos] = s;
}

// ---------------------------------------------------------------------------
// GEMM: g_hs[r,:] = (X[r,:] @ W) * g_dinv[r].
// Tile 64x128, full K. 256 threads, thread tile 8x4 (sX reads are warp-broadcast).
__global__ __launch_bounds__(256, 2)
void gemm_scale_kernel(const float* __restrict__ X, const float* __restrict__ W) {
    extern __shared__ float smem[];
    float* sX = smem;            // [64][128]
    float* sW = smem + 64 * DD;  // [128][128]

    const int tid  = threadIdx.x;
    const int row0 = blockIdx.x * 64;

    {
        const float4* Wv = (const float4*)W;
        float4* sWv = (float4*)sW;
        #pragma unroll
        for (int i = 0; i < 16; i++) sWv[tid + i * 256] = Wv[tid + i * 256];
    }
    {
        #pragma unroll
        for (int i = 0; i < 8; i++) {
            int t4 = tid + i * 256;
            int r  = t4 >> 5;
            int c4 = t4 & 31;
            float4 v = make_float4(0.f, 0.f, 0.f, 0.f);
            if (row0 + r < NN)
                v = ((const float4*)(X + (size_t)(row0 + r) * DD))[c4];
            ((float4*)(sX + r * DD))[c4] = v;
        }
    }
    __syncthreads();

    const int ty = tid >> 5;
    const int tx = tid & 31;

    float c[8][4];
    #pragma unroll
    for (int m = 0; m < 8; m++)
        #pragma unroll
        for (int n = 0; n < 4; n++) c[m][n] = 0.0f;

    #pragma unroll 4
    for (int k = 0; k < DD; k++) {
        float4 b = ((const float4*)(sW + k * DD))[tx];
        float a[8];
        #pragma unroll
        for (int m = 0; m < 8; m++) a[m] = sX[(ty * 8 + m) * DD + k];
        #pragma unroll
        for (int m = 0; m < 8; m++) {
            c[m][0] += a[m] * b.x;
            c[m][1] += a[m] * b.y;
            c[m][2] += a[m] * b.z;
            c[m][3] += a[m] * b.w;
        }
    }

    #pragma unroll
    for (int m = 0; m < 8; m++) {
        int r = row0 + ty * 8 + m;
        if (r < NN) {
            float di = g_dinv[r];
            ((float4*)(g_hs + (size_t)r * DD))[tx] =
                make_float4(c[m][0] * di, c[m][1] * di, c[m][2] * di, c[m][3] * di);
        }
    }
}

// ---------------------------------------------------------------------------
// Gather: one warp per dst node. acc = hs[self] + sum hs[src]; then
// out = acc * dinv[dst] + b (+relu). Register accumulation, no atomics.
template <bool RELU>
__global__ __launch_bounds__(256)
void gather_kernel(const float* __restrict__ bvec, float* __restrict__ out) {
    const int w    = (blockIdx.x * blockDim.x + threadIdx.x) >> 5;
    const int lane = threadIdx.x & 31;
    if (w >= NN) return;

    const float4* hs4 = (const float4*)g_hs;
    const int start = g_rowptr[w];
    const int n     = g_cnt[w];

    float4 acc = hs4[(size_t)w * 32 + lane];   // self loop

    int j = 0;
    for (; j + 4 <= n; j += 4) {
        int s0 = g_srcidx[start + j + 0];
        int s1 = g_srcidx[start + j + 1];
        int s2 = g_srcidx[start + j + 2];
        int s3 = g_srcidx[start + j + 3];
        float4 v0 = hs4[(size_t)s0 * 32 + lane];
        float4 v1 = hs4[(size_t)s1 * 32 + lane];
        float4 v2 = hs4[(size_t)s2 * 32 + lane];
        float4 v3 = hs4[(size_t)s3 * 32 + lane];
        acc.x += v0.x + v1.x + v2.x + v3.x;
        acc.y += v0.y + v1.y + v2.y + v3.y;
        acc.z += v0.z + v1.z + v2.z + v3.z;
        acc.w += v0.w + v1.w + v2.w + v3.w;
    }
    for (; j < n; j++) {
        int s = g_srcidx[start + j];
        float4 v = hs4[(size_t)s * 32 + lane];
        acc.x += v.x; acc.y += v.y; acc.z += v.z; acc.w += v.w;
    }

    const float di = g_dinv[w];
    const float4 b = ((const float4*)bvec)[lane];
    float4 r;
    r.x = acc.x * di + b.x;
    r.y = acc.y * di + b.y;
    r.z = acc.z * di + b.z;
    r.w = acc.w * di + b.w;
    if (RELU) {
        r.x = fmaxf(r.x, 0.f);
        r.y = fmaxf(r.y, 0.f);
        r.z = fmaxf(r.z, 0.f);
        r.w = fmaxf(r.w, 0.f);
    }
    ((float4*)out)[(size_t)w * 32 + lane] = r;
}

// ---------------------------------------------------------------------------
extern "C" void kernel_launch(void* const* d_in, const int* in_sizes, int n_in,
                              void* d_out, int out_size) {
    const float* x  = (const float*)d_in[0];
    const float* W1 = (const float*)d_in[1];
    const float* b1 = (const float*)d_in[2];
    const float* W2 = (const float*)d_in[3];
    const float* b2 = (const float*)d_in[4];
    const void*  ei = d_in[5];
    float* out = (float*)d_out;

    (void)in_sizes; (void)n_in; (void)out_size;

    const int SMEM = 96 * 1024;
    cudaFuncSetAttribute(gemm_scale_kernel,
                         cudaFuncAttributeMaxDynamicSharedMemorySize, SMEM);

    // CSR build (once per replay; reused by both layers)
    detect_kernel<<<1, 256>>>((const int*)ei);
    zero_cnt_kernel<<<(NN + 255) / 256, 256>>>();
    hist_kernel<<<(EE + 255) / 256, 256>>>(ei);
    scan1_kernel<<<NBLK_SCAN, 256>>>();
    scan2_kernel<<<1, 128>>>();
    scan3_kernel<<<(NN + 255) / 256, 256>>>();
    fill_kernel<<<(EE + 255) / 256, 256>>>(ei);

    const int GEMM_BLOCKS   = (NN + 63) / 64;
    const int GATHER_BLOCKS = (NN * 32 + 255) / 256;

    // Layer 1
    gemm_scale_kernel<<<GEMM_BLOCKS, 256, SMEM>>>(x, W1);
    gather_kernel<true><<<GATHER_BLOCKS, 256>>>(b1, out);

    // Layer 2 (reads layer-1 output from d_out, stream-ordered)
    gemm_scale_kernel<<<GEMM_BLOCKS, 256, SMEM>>>(out, W2);
    gather_kernel<false><<<GATHER_BLOCKS, 256>>>(b2, out);
}

// round 4
// speedup vs baseline: 1.7842x; 1.2631x over previous
#include <cuda_runtime.h>
#include <cuda_bf16.h>
#include <cstdint>

#define NN 100000
#define EE 600000
#define DD 128

#define SCAN_CHUNK 1024
#define NBLK_SCAN ((NN + SCAN_CHUNK - 1) / SCAN_CHUNK)   // 98

// Scratch (allocation-free: __device__ globals)
__device__ float g_hs[(size_t)NN * DD];   // (X @ W) * dinv[row]
__device__ float g_dinv[NN];
__device__ int   g_cnt[NN];               // in-degree (excl self loop)
__device__ int   g_rowptr[NN];            // CSR row starts
__device__ int   g_fill[NN];              // fill cursors
__device__ int   g_srcidx[EE];            // CSR column (src) indices
__device__ int   g_bsums[NBLK_SCAN];
__device__ int   g_boffs[NBLK_SCAN];
__device__ int   g_is64;                  // edge_index dtype flag
__device__ uint4 g_Whi[2048];             // W hi bf16 [K=128][N=128] (32KB)
__device__ uint4 g_Wlo[2048];             // W lo bf16 [K=128][N=128] (32KB)

// ---------------------------------------------------------------------------
__device__ __forceinline__ uint32_t smem_u32(const void* p) {
    uint32_t a;
    asm("{ .reg .u64 t; cvta.to.shared.u64 t, %1; cvt.u32.u64 %0, t; }"
        : "=r"(a) : "l"(p));
    return a;
}

#define LDMATRIX_X4(r0, r1, r2, r3, addr) \
    asm volatile("ldmatrix.sync.aligned.m8n8.x4.shared.b16 {%0,%1,%2,%3}, [%4];" \
                 : "=r"(r0), "=r"(r1), "=r"(r2), "=r"(r3) : "r"(addr))
#define LDMATRIX_X4_T(r0, r1, r2, r3, addr) \
    asm volatile("ldmatrix.sync.aligned.m8n8.x4.trans.shared.b16 {%0,%1,%2,%3}, [%4];" \
                 : "=r"(r0), "=r"(r1), "=r"(r2), "=r"(r3) : "r"(addr))
#define MMA_BF16(c, a, b) \
    asm volatile("mma.sync.aligned.m16n8k16.row.col.f32.bf16.bf16.f32 " \
                 "{%0,%1,%2,%3}, {%4,%5,%6,%7}, {%8,%9}, {%0,%1,%2,%3};" \
                 : "+f"((c)[0]), "+f"((c)[1]), "+f"((c)[2]), "+f"((c)[3]) \
                 : "r"((a)[0]), "r"((a)[1]), "r"((a)[2]), "r"((a)[3]), \
                   "r"((b)[0]), "r"((b)[1]))

// ---------------------------------------------------------------------------
// Detect whether edge_index is int64 or int32 (little-endian high words zero).
__global__ void detect_kernel(const int* __restrict__ w) {
    __shared__ int s_any;
    if (threadIdx.x == 0) s_any = 0;
    __syncthreads();
    int acc = 0;
    for (int k = threadIdx.x; k < 4096; k += 256) {
        acc |= w[2 * (k * 137) + 1];
    }
    if (acc) atomicOr(&s_any, 1);
    __syncthreads();
    if (threadIdx.x == 0) g_is64 = (s_any == 0) ? 1 : 0;
}

__device__ __forceinline__ int load_edge(const void* ei, long long pos) {
    if (g_is64) return (int)((const long long*)ei)[pos];
    return ((const int*)ei)[pos];
}

// ---------------------------------------------------------------------------
// CSR build
__global__ void zero_cnt_kernel() {
    int i = blockIdx.x * blockDim.x + threadIdx.x;
    if (i < NN) g_cnt[i] = 0;
}

__global__ void hist_kernel(const void* __restrict__ ei) {
    int e = blockIdx.x * blockDim.x + threadIdx.x;
    if (e >= EE) return;
    int d = load_edge(ei, (long long)EE + e);
    atomicAdd(&g_cnt[d], 1);
}

__global__ __launch_bounds__(256)
void scan1_kernel() {
    __shared__ int s_warp[8];
    const int tid  = threadIdx.x;
    const int base = blockIdx.x * SCAN_CHUNK + tid * 4;

    int v0 = (base + 0 < NN) ? g_cnt[base + 0] : 0;
    int v1 = (base + 1 < NN) ? g_cnt[base + 1] : 0;
    int v2 = (base + 2 < NN) ? g_cnt[base + 2] : 0;
    int v3 = (base + 3 < NN) ? g_cnt[base + 3] : 0;
    int tsum = v0 + v1 + v2 + v3;

    int lane = tid & 31, wid = tid >> 5;
    int incl = tsum;
    #pragma unroll
    for (int o = 1; o < 32; o <<= 1) {
        int n = __shfl_up_sync(0xffffffffu, incl, o);
        if (lane >= o) incl += n;
    }
    if (lane == 31) s_warp[wid] = incl;
    __syncthreads();
    if (wid == 0) {
        int w = (lane < 8) ? s_warp[lane] : 0;
        int wi = w;
        #pragma unroll
        for (int o = 1; o < 8; o <<= 1) {
            int n = __shfl_up_sync(0xffffffffu, wi, o);
            if (lane >= o) wi += n;
        }
        if (lane < 8) s_warp[lane] = wi - w;
        if (lane == 7 && blockIdx.x < NBLK_SCAN) g_bsums[blockIdx.x] = wi;
    }
    __syncthreads();

    int off = s_warp[wid] + (incl - tsum);
    if (base + 0 < NN) g_rowptr[base + 0] = off;
    if (base + 1 < NN) g_rowptr[base + 1] = off + v0;
    if (base + 2 < NN) g_rowptr[base + 2] = off + v0 + v1;
    if (base + 3 < NN) g_rowptr[base + 3] = off + v0 + v1 + v2;
}

__global__ __launch_bounds__(128)
void scan2_kernel() {
    __shared__ int s[128];
    int t = threadIdx.x;
    int v = (t < NBLK_SCAN) ? g_bsums[t] : 0;
    s[t] = v;
    __syncthreads();
    #pragma unroll
    for (int o = 1; o < 128; o <<= 1) {
        int add = (t >= o) ? s[t - o] : 0;
        __syncthreads();
        s[t] += add;
        __syncthreads();
    }
    if (t < NBLK_SCAN) g_boffs[t] = s[t] - v;
}

__global__ void scan3_kernel() {
    int i = blockIdx.x * blockDim.x + threadIdx.x;
    if (i >= NN) return;
    int rp = g_rowptr[i] + g_boffs[i / SCAN_CHUNK];
    g_rowptr[i] = rp;
    g_fill[i]   = rp;
    g_dinv[i]   = rsqrtf((float)(g_cnt[i] + 1));
}

__global__ void fill_kernel(const void* __restrict__ ei) {
    int e = blockIdx.x * blockDim.x + threadIdx.x;
    if (e >= EE) return;
    int s = load_edge(ei, e);
    int d = load_edge(ei, (long long)EE + e);
    int pos = atomicAdd(&g_fill[d], 1);
    g_srcidx[pos] = s;
}

// ---------------------------------------------------------------------------
// W prep: split W fp32 [K=128][N=128] into bf16 hi/lo images, [K][N] row-major.
__global__ void wprep_kernel(const float* __restrict__ W) {
    int t = blockIdx.x * blockDim.x + threadIdx.x;   // 2048: k = t>>4, nchunk = t&15
    if (t >= 2048) return;
    const float* wp = W + (t >> 4) * DD + (t & 15) * 8;
    unsigned hi[8], lo[8];
    #pragma unroll
    for (int j = 0; j < 8; j++) {
        float x = wp[j];
        __nv_bfloat16 h = __float2bfloat16_rn(x);
        float rem = x - __bfloat162float(h);
        __nv_bfloat16 l = __float2bfloat16_rn(rem);
        hi[j] = (unsigned)__bfloat16_as_ushort(h);
        lo[j] = (unsigned)__bfloat16_as_ushort(l);
    }
    g_Whi[t] = make_uint4(hi[0] | (hi[1] << 16), hi[2] | (hi[3] << 16),
                          hi[4] | (hi[5] << 16), hi[6] | (hi[7] << 16));
    g_Wlo[t] = make_uint4(lo[0] | (lo[1] << 16), lo[2] | (lo[3] << 16),
                          lo[4] | (lo[5] << 16), lo[6] | (lo[7] << 16));
}

// ---------------------------------------------------------------------------
// mma.sync split-bf16 GEMM: per CTA 128x128 tile, K=128.
// g_hs[r,:] = (X[r,:] @ W) * g_dinv[r].
// Smem layout (bf16, row stride 136 elems = 272B, ldmatrix conflict-free):
//   Xhi @ 0, Xlo @ 34816, Whi @ 69632, Wlo @ 104448; total 139264 B.
#define XSTR 136
#define SM_XLO 34816
#define SM_WHI 69632
#define SM_WLO 104448
#define GEMM_SMEM 139264

__global__ __launch_bounds__(256, 1)
void gemm_bf16_kernel(const float* __restrict__ X) {
    extern __shared__ __align__(16) char sm[];
    const int tid  = threadIdx.x;
    const int warp = tid >> 5;
    const int lane = tid & 31;
    const int row0 = blockIdx.x * 128;

    // --- W images -> smem (padded rows) ---
    {
        #pragma unroll
        for (int i = 0; i < 8; i++) {
            int idx = tid + i * 256;          // uint4 chunk: row = idx>>4, chunk = idx&15
            int off = (idx >> 4) * (XSTR * 2) + (idx & 15) * 16;
            *(uint4*)(sm + SM_WHI + off) = g_Whi[idx];
            *(uint4*)(sm + SM_WLO + off) = g_Wlo[idx];
        }
    }
    // --- X tile: fp32 -> bf16 hi/lo, padded rows ---
    {
        int r = tid >> 1;
        int khalf = (tid & 1) * 64;
        bool valid = (row0 + r) < NN;
        const float4* xp = (const float4*)(X + (size_t)(row0 + r) * DD);
        #pragma unroll
        for (int kb = 0; kb < 8; kb++) {
            int k = khalf + kb * 8;
            float4 a = valid ? xp[k >> 2] : make_float4(0.f, 0.f, 0.f, 0.f);
            float4 b = valid ? xp[(k >> 2) + 1] : make_float4(0.f, 0.f, 0.f, 0.f);
            float f[8] = {a.x, a.y, a.z, a.w, b.x, b.y, b.z, b.w};
            unsigned hi[8], lo[8];
            #pragma unroll
            for (int j = 0; j < 8; j++) {
                __nv_bfloat16 h = __float2bfloat16_rn(f[j]);
                float rem = f[j] - __bfloat162float(h);
                __nv_bfloat16 l = __float2bfloat16_rn(rem);
                hi[j] = (unsigned)__bfloat16_as_ushort(h);
                lo[j] = (unsigned)__bfloat16_as_ushort(l);
            }
            int off = r * (XSTR * 2) + k * 2;
            *(uint4*)(sm + off) =
                make_uint4(hi[0] | (hi[1] << 16), hi[2] | (hi[3] << 16),
                           hi[4] | (hi[5] << 16), hi[6] | (hi[7] << 16));
            *(uint4*)(sm + SM_XLO + off) =
                make_uint4(lo[0] | (lo[1] << 16), lo[2] | (lo[3] << 16),
                           lo[4] | (lo[5] << 16), lo[6] | (lo[7] << 16));
        }
    }
    __syncthreads();

    // --- warp tiling: 4x2 warps, each 32 rows x 64 cols ---
    const int m_base = (warp >> 1) * 32;
    const int n_base = (warp & 1) * 64;

    const uint32_t sbase = smem_u32(sm);
    // ldmatrix lane offsets
    const int a_row = (lane & 7) + ((lane >> 3) & 1) * 8;   // + mt*16
    const int a_col = (lane >> 4) * 8;                      // + k0
    const int b_krow = (lane & 7) + ((lane >> 3) & 1) * 8;  // + k0
    const int b_ncol = (lane >> 4) * 8;                     // + n_base + jp*16

    float acc[2][8][4];
    #pragma unroll
    for (int mt = 0; mt < 2; mt++)
        #pragma unroll
        for (int j = 0; j < 8; j++)
            #pragma unroll
            for (int q = 0; q < 4; q++) acc[mt][j][q] = 0.f;

    #pragma unroll 2
    for (int ks = 0; ks < 8; ks++) {
        const int k0 = ks * 16;
        uint32_t ahi[2][4], alo[2][4], bhi[8][2], blo[8][2];
        #pragma unroll
        for (int mt = 0; mt < 2; mt++) {
            uint32_t aoff = ((m_base + mt * 16 + a_row) * XSTR + k0 + a_col) * 2;
            LDMATRIX_X4(ahi[mt][0], ahi[mt][1], ahi[mt][2], ahi[mt][3], sbase + aoff);
            LDMATRIX_X4(alo[mt][0], alo[mt][1], alo[mt][2], alo[mt][3],
                        sbase + SM_XLO + aoff);
        }
        #pragma unroll
        for (int jp = 0; jp < 4; jp++) {
            uint32_t boff = ((k0 + b_krow) * XSTR + n_base + jp * 16 + b_ncol) * 2;
            LDMATRIX_X4_T(bhi[jp * 2][0], bhi[jp * 2][1],
                          bhi[jp * 2 + 1][0], bhi[jp * 2 + 1][1],
                          sbase + SM_WHI + boff);
            LDMATRIX_X4_T(blo[jp * 2][0], blo[jp * 2][1],
                          blo[jp * 2 + 1][0], blo[jp * 2 + 1][1],
                          sbase + SM_WLO + boff);
        }
        #pragma unroll
        for (int mt = 0; mt < 2; mt++)
            #pragma unroll
            for (int j = 0; j < 8; j++) {
                MMA_BF16(acc[mt][j], ahi[mt], bhi[j]);
                MMA_BF16(acc[mt][j], ahi[mt], blo[j]);
                MMA_BF16(acc[mt][j], alo[mt], bhi[j]);
            }
    }

    // --- epilogue: direct float2 stores, dinv fused ---
    #pragma unroll
    for (int mt = 0; mt < 2; mt++) {
        int r0 = row0 + m_base + mt * 16 + (lane >> 2);
        int r1 = r0 + 8;
        float di0 = (r0 < NN) ? g_dinv[r0] : 0.f;
        float di1 = (r1 < NN) ? g_dinv[r1] : 0.f;
        #pragma unroll
        for (int j = 0; j < 8; j++) {
            int c = n_base + j * 8 + (lane & 3) * 2;
            if (r0 < NN)
                *(float2*)(g_hs + (size_t)r0 * DD + c) =
                    make_float2(acc[mt][j][0] * di0, acc[mt][j][1] * di0);
            if (r1 < NN)
                *(float2*)(g_hs + (size_t)r1 * DD + c) =
                    make_float2(acc[mt][j][2] * di1, acc[mt][j][3] * di1);
        }
    }
}

// ---------------------------------------------------------------------------
// Gather: one warp per dst node; register accumulation, fused bias/relu.
template <bool RELU>
__global__ __launch_bounds__(256)
void gather_kernel(const float* __restrict__ bvec, float* __restrict__ out) {
    const int w    = (blockIdx.x * blockDim.x + threadIdx.x) >> 5;
    const int lane = threadIdx.x & 31;
    if (w >= NN) return;

    const float4* hs4 = (const float4*)g_hs;
    const int start = g_rowptr[w];
    const int n     = g_cnt[w];

    float4 acc = hs4[(size_t)w * 32 + lane];   // self loop

    int j = 0;
    for (; j + 4 <= n; j += 4) {
        int s0 = g_srcidx[start + j + 0];
        int s1 = g_srcidx[start + j + 1];
        int s2 = g_srcidx[start + j + 2];
        int s3 = g_srcidx[start + j + 3];
        float4 v0 = hs4[(size_t)s0 * 32 + lane];
        float4 v1 = hs4[(size_t)s1 * 32 + lane];
        float4 v2 = hs4[(size_t)s2 * 32 + lane];
        float4 v3 = hs4[(size_t)s3 * 32 + lane];
        acc.x += v0.x + v1.x + v2.x + v3.x;
        acc.y += v0.y + v1.y + v2.y + v3.y;
        acc.z += v0.z + v1.z + v2.z + v3.z;
        acc.w += v0.w + v1.w + v2.w + v3.w;
    }
    for (; j < n; j++) {
        int s = g_srcidx[start + j];
        float4 v = hs4[(size_t)s * 32 + lane];
        acc.x += v.x; acc.y += v.y; acc.z += v.z; acc.w += v.w;
    }

    const float di = g_dinv[w];
    const float4 b = ((const float4*)bvec)[lane];
    float4 r;
    r.x = acc.x * di + b.x;
    r.y = acc.y * di + b.y;
    r.z = acc.z * di + b.z;
    r.w = acc.w * di + b.w;
    if (RELU) {
        r.x = fmaxf(r.x, 0.f);
        r.y = fmaxf(r.y, 0.f);
        r.z = fmaxf(r.z, 0.f);
        r.w = fmaxf(r.w, 0.f);
    }
    ((float4*)out)[(size_t)w * 32 + lane] = r;
}

// ---------------------------------------------------------------------------
extern "C" void kernel_launch(void* const* d_in, const int* in_sizes, int n_in,
                              void* d_out, int out_size) {
    const float* x  = (const float*)d_in[0];
    const float* W1 = (const float*)d_in[1];
    const float* b1 = (const float*)d_in[2];
    const float* W2 = (const float*)d_in[3];
    const float* b2 = (const float*)d_in[4];
    const void*  ei = d_in[5];
    float* out = (float*)d_out;

    (void)in_sizes; (void)n_in; (void)out_size;

    cudaFuncSetAttribute(gemm_bf16_kernel,
                         cudaFuncAttributeMaxDynamicSharedMemorySize, GEMM_SMEM);

    // CSR build (once per replay; reused by both layers)
    detect_kernel<<<1, 256>>>((const int*)ei);
    zero_cnt_kernel<<<(NN + 255) / 256, 256>>>();
    hist_kernel<<<(EE + 255) / 256, 256>>>(ei);
    scan1_kernel<<<NBLK_SCAN, 256>>>();
    scan2_kernel<<<1, 128>>>();
    scan3_kernel<<<(NN + 255) / 256, 256>>>();
    fill_kernel<<<(EE + 255) / 256, 256>>>(ei);

    const int GEMM_BLOCKS   = (NN + 127) / 128;     // 782
    const int GATHER_BLOCKS = (NN * 32 + 255) / 256;

    // Layer 1
    wprep_kernel<<<8, 256>>>(W1);
    gemm_bf16_kernel<<<GEMM_BLOCKS, 256, GEMM_SMEM>>>(x);
    gather_kernel<true><<<GATHER_BLOCKS, 256>>>(b1, out);

    // Layer 2 (reads layer-1 output from d_out, stream-ordered)
    wprep_kernel<<<8, 256>>>(W2);
    gemm_bf16_kernel<<<GEMM_BLOCKS, 256, GEMM_SMEM>>>(out);
    gather_kernel<false><<<GATHER_BLOCKS, 256>>>(b2, out);
}